// round 1
// baseline (speedup 1.0000x reference)
#include <cuda_runtime.h>
#include <cstdint>

// out[r][c] = in[2r+1][2c+1], in: 8192x8192 f32, out: 4096x4096 f32.
// Each thread writes one float4 of output (4 consecutive output columns),
// reading two aligned float4 from the corresponding odd input row.
//
// Output cols 4t..4t+3  -> input cols 8t+1, 8t+3, 8t+5, 8t+7
//   = float4 at in_row + 8t   (.y = 8t+1, .w = 8t+3)
//   + float4 at in_row + 8t+4 (.y = 8t+5, .w = 8t+7)

static constexpr int N_IN  = 8192;
static constexpr int N_OUT = 4096;
static constexpr int VECS_PER_ROW = N_OUT / 4;   // 1024 float4 per output row

__global__ void downsample2x_kernel(const float4* __restrict__ in,
                                    float4* __restrict__ out) {
    // Linear thread id over (row, vec) space.
    unsigned tid = blockIdx.x * blockDim.x + threadIdx.x;   // 0 .. 4096*1024-1
    unsigned row = tid >> 10;          // / VECS_PER_ROW
    unsigned vec = tid & 1023;         // % VECS_PER_ROW

    // Input row (2*row + 1), as float4 pointer: row stride = 8192 floats = 2048 float4
    const float4* in_row = in + (size_t)(2u * row + 1u) * (N_IN / 4);

    float4 a = in_row[2u * vec];
    float4 b = in_row[2u * vec + 1u];

    float4 o;
    o.x = a.y;
    o.y = a.w;
    o.z = b.y;
    o.w = b.w;

    out[(size_t)row * VECS_PER_ROW + vec] = o;
}

extern "C" void kernel_launch(void* const* d_in, const int* in_sizes, int n_in,
                              void* d_out, int out_size) {
    const float4* in  = (const float4*)d_in[0];
    float4*       out = (float4*)d_out;

    const int total_threads = N_OUT * VECS_PER_ROW;  // 4096 * 1024 = 4,194,304
    const int block = 256;
    const int grid  = total_threads / block;         // 16384

    downsample2x_kernel<<<grid, block>>>(in, out);
}